// round 1
// baseline (speedup 1.0000x reference)
#include <cuda_runtime.h>
#include <cuda_bf16.h>

// Problem constants (fixed by the reference)
constexpr int B_ = 2048;   // batch
constexpr int Z_ = 128;    // z dim (K of layer 1)
constexpr int H_ = 1024;   // hidden (N of layer 1, K of layer 2)
constexpr int O_ = 3072;   // output (N of layer 2)
constexpr int E_ = 8;      // experts

// Scratch (device globals; no allocations allowed)
__device__ int   g_idx[B_];
__device__ int   g_counts[E_];
__device__ int   g_offsets[E_ + 1];
__device__ int   g_cursor[E_];
__device__ int   g_perm[B_];
__device__ float g_h[B_ * H_];   // hidden activations, indexed by ORIGINAL row

// ---------------------------------------------------------------------------
// Routing: hash = mod(sum_k floor(|z|*1000), 8). All values are exact
// integers in fp32 (< 2^24), so any summation order matches JAX bit-exactly.
// ---------------------------------------------------------------------------
__global__ void zero_kernel() {
    int t = threadIdx.x;
    if (t < E_) { g_counts[t] = 0; g_cursor[t] = 0; }
}

__global__ void route_kernel(const float* __restrict__ z) {
    int i = blockIdx.x * blockDim.x + threadIdx.x;
    if (i >= B_) return;
    const float* zr = z + (size_t)i * Z_;
    float s = 0.0f;
    #pragma unroll 8
    for (int k = 0; k < Z_; k++)
        s += floorf(fabsf(zr[k]) * 1000.0f);
    int e = ((int)s) & (E_ - 1);   // mod 8, s >= 0
    g_idx[i] = e;
    atomicAdd(&g_counts[e], 1);
}

__global__ void scan_kernel() {
    int o = 0;
    g_offsets[0] = 0;
    for (int e = 0; e < E_; e++) { o += g_counts[e]; g_offsets[e + 1] = o; }
}

__global__ void scatter_kernel() {
    int i = blockIdx.x * blockDim.x + threadIdx.x;
    if (i >= B_) return;
    int e = g_idx[i];
    int pos = g_offsets[e] + atomicAdd(&g_cursor[e], 1);
    g_perm[pos] = i;
}

// ---------------------------------------------------------------------------
// Grouped GEMM: for expert e = blockIdx.z, rows perm[offs[e] + row0 ..] of A:
//   C[orig, n] = act( sum_k A[orig, k] * Bw[e, k, n] + bias[e, n] )
// BM = BN = 128, BK = 16, 256 threads, 8x8 micro-tile per thread.
// K == lda(A) == row stride of A; N == ldc(C). Both K and N are multiples
// of 16 / 128 respectively for this problem.
// Results per output element depend only on (row, n, e) -> deterministic
// regardless of the (atomic) ordering inside each expert's perm segment.
// ---------------------------------------------------------------------------
template <bool RELU>
__global__ __launch_bounds__(256, 2)
void moe_gemm(const float* __restrict__ A, const float* __restrict__ Bw,
              const float* __restrict__ bias, float* __restrict__ C,
              int K, int N) {
    const int e    = blockIdx.z;
    const int off  = g_offsets[e];
    const int cnt  = g_offsets[e + 1] - off;
    const int row0 = blockIdx.y * 128;
    if (row0 >= cnt) return;
    const int mvalid = min(128, cnt - row0);
    const int n0 = blockIdx.x * 128;

    const float* Be = Bw + (size_t)e * K * N;
    const float* be = bias + (size_t)e * N;

    __shared__ float As[16][129];   // [k][m], padded: conflict-free transpose
    __shared__ float Bs[16][128];   // [k][n]
    __shared__ int   perm_s[128];

    const int t = threadIdx.x;
    if (t < 128)
        perm_s[t] = (t < mvalid) ? g_perm[off + row0 + t] : 0;
    __syncthreads();

    const int tx = t & 15;    // n-direction
    const int ty = t >> 4;    // m-direction
    float acc[8][8] = {};

    for (int k0 = 0; k0 < K; k0 += 16) {
        // Load A tile (128 x 16), transposed into As[k][m]
        #pragma unroll
        for (int l = 0; l < 2; l++) {
            int ft = t + l * 256;            // float4 index, 0..511
            int m  = ft >> 2;
            int k4 = ft & 3;
            float4 v = make_float4(0.f, 0.f, 0.f, 0.f);
            if (m < mvalid)
                v = *(const float4*)(A + (size_t)perm_s[m] * K + k0 + k4 * 4);
            As[k4 * 4 + 0][m] = v.x;
            As[k4 * 4 + 1][m] = v.y;
            As[k4 * 4 + 2][m] = v.z;
            As[k4 * 4 + 3][m] = v.w;
        }
        // Load B tile (16 x 128), direct
        #pragma unroll
        for (int l = 0; l < 2; l++) {
            int ft = t + l * 256;
            int k  = ft >> 5;
            int n4 = ft & 31;
            *(float4*)&Bs[k][n4 * 4] =
                *(const float4*)(Be + (size_t)(k0 + k) * N + n0 + n4 * 4);
        }
        __syncthreads();

        #pragma unroll
        for (int kk = 0; kk < 16; kk++) {
            float a[8], b[8];
            #pragma unroll
            for (int i = 0; i < 8; i++) a[i] = As[kk][ty * 8 + i];
            #pragma unroll
            for (int j = 0; j < 8; j++) b[j] = Bs[kk][tx * 8 + j];
            #pragma unroll
            for (int i = 0; i < 8; i++)
                #pragma unroll
                for (int j = 0; j < 8; j++)
                    acc[i][j] += a[i] * b[j];
        }
        __syncthreads();
    }

    // Epilogue: bias (+ReLU), scatter back to original rows
    #pragma unroll
    for (int i = 0; i < 8; i++) {
        int m = ty * 8 + i;
        if (m < mvalid) {
            int orig = perm_s[m];
            float* Crow = C + (size_t)orig * N + n0 + tx * 8;
            #pragma unroll
            for (int j = 0; j < 8; j++) {
                float v = acc[i][j] + be[n0 + tx * 8 + j];
                if (RELU) v = fmaxf(v, 0.0f);
                Crow[j] = v;
            }
        }
    }
}

// ---------------------------------------------------------------------------
extern "C" void kernel_launch(void* const* d_in, const int* in_sizes, int n_in,
                              void* d_out, int out_size) {
    const float* z  = (const float*)d_in[0];   // [B, Z]
    const float* W1 = (const float*)d_in[1];   // [E, Z, H]
    const float* b1 = (const float*)d_in[2];   // [E, H]
    const float* W2 = (const float*)d_in[3];   // [E, H, O]
    const float* b2 = (const float*)d_in[4];   // [E, O]
    float* out = (float*)d_out;                // [B, O]

    zero_kernel<<<1, 32>>>();
    route_kernel<<<B_ / 256, 256>>>(z);
    scan_kernel<<<1, 1>>>();
    scatter_kernel<<<B_ / 256, 256>>>();

    // Layer 1: h = relu(z @ W1[e] + b1[e]);  M=cnt, N=1024, K=128
    {
        float* hptr;
        cudaGetSymbolAddress((void**)&hptr, g_h);
        dim3 grid(H_ / 128, B_ / 128, E_);
        moe_gemm<true><<<grid, 256>>>(z, W1, b1, hptr, Z_, H_);
    }
    // Layer 2: y = h @ W2[e] + b2[e];        M=cnt, N=3072, K=1024
    {
        float* hptr;
        cudaGetSymbolAddress((void**)&hptr, g_h);
        dim3 grid(O_ / 128, B_ / 128, E_);
        moe_gemm<false><<<grid, 256>>>(hptr, W2, b2, out, H_, O_);
    }
}